// round 1
// baseline (speedup 1.0000x reference)
#include <cuda_runtime.h>
#include <cstdint>
#include <math.h>

// Problem constants
#define TOK   200704            // 64 * 56 * 56 tokens
#define CDIM  384
#define NHEAD 12
#define DHEAD 32
#define NWIN  4096               // 64 images * 64 windows
#define NPOS  49
#define HID   1536

// ---------------- scratch (static device buffers; no allocations) -------------
__device__ float g_xw [(size_t)TOK * CDIM];       // LN1 + roll + window-partitioned
__device__ float g_qkv[(size_t)TOK * 3 * CDIM];   // qkv projection
__device__ float g_att[(size_t)TOK * CDIM];       // attention output (head-concat)
__device__ float g_x2 [(size_t)TOK * CDIM];       // x + attn branch (token layout)
__device__ float g_xn2[(size_t)TOK * CDIM];       // LN2 output
__device__ float g_h1 [(size_t)TOK * HID];        // gelu(mlp1)

// ---------------- LayerNorm (optionally fused roll + window partition) --------
template <bool REMAP>
__global__ void ln_kernel(const float* __restrict__ xin,
                          const float* __restrict__ sc,
                          const float* __restrict__ bi,
                          float* __restrict__ xout) {
    int t = blockIdx.x;                 // destination token (window layout if REMAP)
    size_t src;
    if (REMAP) {
        int win = t / NPOS, npos = t - win * NPOS;
        int b = win >> 6, wy = (win >> 3) & 7, wx = win & 7;
        int py = npos / 7, px = npos - py * 7;
        int sy = wy * 7 + py + 3; if (sy >= 56) sy -= 56;   // roll(-3)
        int sx = wx * 7 + px + 3; if (sx >= 56) sx -= 56;
        src = (size_t)b * 3136 + sy * 56 + sx;
    } else {
        src = (size_t)t;
    }
    const float* xp = xin + src * CDIM;
    int tid = threadIdx.x;              // 128 threads, 3 elems each
    float v0 = xp[tid], v1 = xp[tid + 128], v2 = xp[tid + 256];
    float s  = v0 + v1 + v2;
    float s2 = v0 * v0 + v1 * v1 + v2 * v2;
#pragma unroll
    for (int o = 16; o > 0; o >>= 1) {
        s  += __shfl_down_sync(0xffffffffu, s,  o);
        s2 += __shfl_down_sync(0xffffffffu, s2, o);
    }
    __shared__ float sh[8];
    int w = tid >> 5;
    if ((tid & 31) == 0) { sh[w] = s; sh[4 + w] = s2; }
    __syncthreads();
    float S  = sh[0] + sh[1] + sh[2] + sh[3];
    float S2 = sh[4] + sh[5] + sh[6] + sh[7];
    float mu  = S * (1.0f / CDIM);
    float var = S2 * (1.0f / CDIM) - mu * mu;
    float r = rsqrtf(var + 1e-6f);
    float* op = xout + (size_t)t * CDIM;
    op[tid]       = (v0 - mu) * r * sc[tid]       + bi[tid];
    op[tid + 128] = (v1 - mu) * r * sc[tid + 128] + bi[tid + 128];
    op[tid + 256] = (v2 - mu) * r * sc[tid + 256] + bi[tid + 256];
}

// ---------------- windowed multi-head attention -------------------------------
// one block per (window, head); 64 threads (49 active in compute phase)
__global__ void attn_kernel(const float* __restrict__ qkv, float* __restrict__ out) {
    int blk  = blockIdx.x;
    int win  = blk / NHEAD;
    int head = blk - win * NHEAD;
    int wy = (win >> 3) & 7, wx = win & 7;

    __shared__ float ks[NPOS * DHEAD];
    __shared__ float vs[NPOS * DHEAD];
    __shared__ float sc[NPOS * 53];      // padded rows -> conflict-free
    __shared__ int   rg[NPOS];

    int tid = threadIdx.x;
    const float* base = qkv + (size_t)win * NPOS * (3 * CDIM) + head * DHEAD;

    for (int i = tid; i < NPOS * DHEAD; i += 64) {
        int n = i >> 5, d = i & 31;
        ks[i] = base[(size_t)n * (3 * CDIM) + CDIM     + d];
        vs[i] = base[(size_t)n * (3 * CDIM) + 2 * CDIM + d];
    }
    if (tid < NPOS) {
        int py = tid / 7, px = tid - py * 7;
        int hy = wy * 7 + py, hx = wx * 7 + px;
        int cy = hy < 49 ? 0 : (hy < 53 ? 1 : 2);
        int cx = hx < 49 ? 0 : (hx < 53 ? 1 : 2);
        rg[tid] = cy * 3 + cx;
    }
    __syncthreads();

    if (tid < NPOS) {
        // q row in registers
        float q[DHEAD];
        const float* qp = base + (size_t)tid * (3 * CDIM);
#pragma unroll
        for (int d = 0; d < DHEAD; d += 4) {
            float4 t4 = *(const float4*)(qp + d);
            q[d] = t4.x; q[d + 1] = t4.y; q[d + 2] = t4.z; q[d + 3] = t4.w;
        }
        int rn = rg[tid];
        const float scale = 0.17677669529663687f;   // 1/sqrt(32)
        float mx = -1e30f;
        for (int m = 0; m < NPOS; ++m) {
            const float4* kp = (const float4*)&ks[m * DHEAD];
            float s = 0.f;
#pragma unroll
            for (int d8 = 0; d8 < 8; ++d8) {
                float4 kv = kp[d8];
                s += q[d8 * 4] * kv.x + q[d8 * 4 + 1] * kv.y
                   + q[d8 * 4 + 2] * kv.z + q[d8 * 4 + 3] * kv.w;
            }
            s *= scale;
            if (rg[m] != rn) s -= 100.0f;
            sc[tid * 53 + m] = s;
            mx = fmaxf(mx, s);
        }
        float sum = 0.f;
        for (int m = 0; m < NPOS; ++m) {
            float p = __expf(sc[tid * 53 + m] - mx);
            sc[tid * 53 + m] = p;
            sum += p;
        }
        float inv = 1.0f / sum;
        float acc[DHEAD];
#pragma unroll
        for (int d = 0; d < DHEAD; ++d) acc[d] = 0.f;
        for (int m = 0; m < NPOS; ++m) {
            float p = sc[tid * 53 + m];
            const float4* vp = (const float4*)&vs[m * DHEAD];
#pragma unroll
            for (int d8 = 0; d8 < 8; ++d8) {
                float4 vv = vp[d8];
                acc[d8 * 4]     += p * vv.x;
                acc[d8 * 4 + 1] += p * vv.y;
                acc[d8 * 4 + 2] += p * vv.z;
                acc[d8 * 4 + 3] += p * vv.w;
            }
        }
        float* op = out + (size_t)(win * NPOS + tid) * CDIM + head * DHEAD;
#pragma unroll
        for (int d = 0; d < DHEAD; d += 4) {
            float4 o4 = make_float4(acc[d] * inv, acc[d + 1] * inv,
                                    acc[d + 2] * inv, acc[d + 3] * inv);
            *(float4*)(op + d) = o4;
        }
    }
}

// ---------------- generic fp32 GEMM with fused epilogues -----------------------
// EPI 0: +bias          (qkv)
// EPI 1: gelu(+bias)    (mlp1)
// EPI 2: +bias, window-reverse + roll(+3) scatter, +residual x   (proj)
// EPI 3: +bias, +residual (row-aligned)                           (mlp2)
__device__ __forceinline__ float gelu_tanh(float v) {
    float u = 0.7978845608028654f * (v + 0.044715f * v * v * v);
    return 0.5f * v * (1.0f + tanhf(u));
}

template <int EPI>
__global__ __launch_bounds__(256)
void sgemm(const float* __restrict__ A, const float* __restrict__ Bm,
           const float* __restrict__ bias, float* __restrict__ Cout,
           const float* __restrict__ res, int M, int Nn, int K) {
    const int BM = 128, BN = 128, BK = 8;
    __shared__ float As[BK][BM];
    __shared__ float Bs[BK][BN];
    int bx = blockIdx.x, by = blockIdx.y;
    int tid = threadIdx.x;
    int tx = tid & 15, ty = tid >> 4;

    const float* Aptr = A + (size_t)by * BM * K;
    const float* Bptr = Bm + bx * BN;

    int arow = tid >> 1, acol = (tid & 1) * 4;
    int brow = tid >> 5, bcol = (tid & 31) * 4;

    float acc[8][8] = {};

    for (int k0 = 0; k0 < K; k0 += BK) {
        float4 a4 = *(const float4*)(Aptr + (size_t)arow * K + k0 + acol);
        float4 b4 = *(const float4*)(Bptr + (size_t)(k0 + brow) * Nn + bcol);
        As[acol + 0][arow] = a4.x;
        As[acol + 1][arow] = a4.y;
        As[acol + 2][arow] = a4.z;
        As[acol + 3][arow] = a4.w;
        *(float4*)&Bs[brow][bcol] = b4;
        __syncthreads();
#pragma unroll
        for (int kk = 0; kk < BK; ++kk) {
            float4 a0 = *(const float4*)&As[kk][ty * 8];
            float4 a1 = *(const float4*)&As[kk][ty * 8 + 4];
            float4 b0 = *(const float4*)&Bs[kk][tx * 8];
            float4 b1 = *(const float4*)&Bs[kk][tx * 8 + 4];
            float ra[8] = {a0.x, a0.y, a0.z, a0.w, a1.x, a1.y, a1.z, a1.w};
            float rb[8] = {b0.x, b0.y, b0.z, b0.w, b1.x, b1.y, b1.z, b1.w};
#pragma unroll
            for (int i = 0; i < 8; ++i)
#pragma unroll
                for (int j = 0; j < 8; ++j)
                    acc[i][j] += ra[i] * rb[j];
        }
        __syncthreads();
    }

#pragma unroll
    for (int i = 0; i < 8; ++i) {
        int m = by * BM + ty * 8 + i;
        float* orow;
        const float* rrow = nullptr;
        if (EPI == 2) {
            int win = m / NPOS, npos = m - win * NPOS;
            int b = win >> 6, wy = (win >> 3) & 7, wx = win & 7;
            int py = npos / 7, px = npos - py * 7;
            int yy = wy * 7 + py + 3; if (yy >= 56) yy -= 56;   // roll(+3)
            int xx = wx * 7 + px + 3; if (xx >= 56) xx -= 56;
            size_t drow = ((size_t)b * 3136 + yy * 56 + xx) * (size_t)Nn;
            orow = Cout + drow;
            rrow = res + drow;
        } else {
            orow = Cout + (size_t)m * Nn;
            if (EPI == 3) rrow = res + (size_t)m * Nn;
        }
#pragma unroll
        for (int j = 0; j < 8; ++j) {
            int n = bx * BN + tx * 8 + j;
            float v = acc[i][j] + bias[n];
            if (EPI == 1) v = gelu_tanh(v);
            if (EPI == 2 || EPI == 3) v += rrow[n];
            orow[n] = v;
        }
    }
}

// ---------------- launch ------------------------------------------------------
extern "C" void kernel_launch(void* const* d_in, const int* in_sizes, int n_in,
                              void* d_out, int out_size) {
    const float* x     = (const float*)d_in[0];
    const float* n1s   = (const float*)d_in[1];
    const float* n1b   = (const float*)d_in[2];
    const float* qkvw  = (const float*)d_in[3];
    const float* qkvb  = (const float*)d_in[4];
    const float* projw = (const float*)d_in[5];
    const float* projb = (const float*)d_in[6];
    const float* n2s   = (const float*)d_in[7];
    const float* n2b   = (const float*)d_in[8];
    const float* w1    = (const float*)d_in[9];
    const float* b1    = (const float*)d_in[10];
    const float* w2    = (const float*)d_in[11];
    const float* b2    = (const float*)d_in[12];
    float* out = (float*)d_out;

    float *xw, *qkv, *att, *x2, *xn2, *h1;
    cudaGetSymbolAddress((void**)&xw,  g_xw);
    cudaGetSymbolAddress((void**)&qkv, g_qkv);
    cudaGetSymbolAddress((void**)&att, g_att);
    cudaGetSymbolAddress((void**)&x2,  g_x2);
    cudaGetSymbolAddress((void**)&xn2, g_xn2);
    cudaGetSymbolAddress((void**)&h1,  g_h1);

    // 1. LN1 + roll + window partition
    ln_kernel<true><<<TOK, 128>>>(x, n1s, n1b, xw);
    // 2. QKV projection: (200704 x 384) @ (384 x 1152)
    sgemm<0><<<dim3(1152 / 128, TOK / 128), 256>>>(xw, qkvw, qkvb, qkv, nullptr,
                                                   TOK, 3 * CDIM, CDIM);
    // 3. windowed attention
    attn_kernel<<<NWIN * NHEAD, 64>>>(qkv, att);
    // 4. proj + window reverse + roll back + residual -> x2
    sgemm<2><<<dim3(CDIM / 128, TOK / 128), 256>>>(att, projw, projb, x2, x,
                                                   TOK, CDIM, CDIM);
    // 5. LN2
    ln_kernel<false><<<TOK, 128>>>(x2, n2s, n2b, xn2);
    // 6. MLP1 + gelu
    sgemm<1><<<dim3(HID / 128, TOK / 128), 256>>>(xn2, w1, b1, h1, nullptr,
                                                  TOK, HID, CDIM);
    // 7. MLP2 + residual -> output
    sgemm<3><<<dim3(CDIM / 128, TOK / 128), 256>>>(h1, w2, b2, out, x2,
                                                   TOK, CDIM, HID);
}

// round 3
// speedup vs baseline: 4.4974x; 4.4974x over previous
#include <cuda_runtime.h>
#include <cuda_bf16.h>
#include <cstdint>
#include <math.h>

#define TOK   200704
#define CDIM  384
#define NHEAD 12
#define DHEAD 32
#define NWIN  4096
#define NPOS  49
#define HID   1536

// ---------------- static scratch ----------------------------------------------
__device__ __nv_bfloat16 g_xw [(size_t)TOK * CDIM];
__device__ __nv_bfloat16 g_qkv[(size_t)TOK * 3 * CDIM];
__device__ __nv_bfloat16 g_att[(size_t)TOK * CDIM];
__device__ float         g_x2 [(size_t)TOK * CDIM];
__device__ __nv_bfloat16 g_xn2[(size_t)TOK * CDIM];
__device__ __nv_bfloat16 g_h1 [(size_t)TOK * HID];
__device__ __nv_bfloat16 g_wqkv [CDIM * 3 * CDIM];   // [384][1152]  (K-major, same as input)
__device__ __nv_bfloat16 g_wproj[CDIM * CDIM];       // [384][384]
__device__ __nv_bfloat16 g_wm1  [CDIM * HID];        // [384][1536]
__device__ __nv_bfloat16 g_wm2  [HID * CDIM];        // [1536][384]

// ---------------- helpers -------------------------------------------------------
__device__ __forceinline__ uint32_t smem_u32(const void* p) {
    uint32_t a;
    asm("{ .reg .u64 t; cvta.to.shared.u64 t, %1; cvt.u32.u64 %0, t; }" : "=r"(a) : "l"(p));
    return a;
}
__device__ __forceinline__ void cp16(uint32_t dst, const void* src) {
    asm volatile("cp.async.cg.shared.global [%0], [%1], 16;" :: "r"(dst), "l"(src));
}
#define CP_COMMIT() asm volatile("cp.async.commit_group;" ::: "memory")
#define CP_WAIT(n)  asm volatile("cp.async.wait_group %0;" :: "n"(n) : "memory")

__device__ __forceinline__ void ldsm4(uint32_t* r, uint32_t addr) {
    asm volatile("ldmatrix.sync.aligned.m8n8.x4.shared.b16 {%0,%1,%2,%3}, [%4];"
                 : "=r"(r[0]), "=r"(r[1]), "=r"(r[2]), "=r"(r[3]) : "r"(addr));
}
__device__ __forceinline__ void ldsm4t(uint32_t* r, uint32_t addr) {
    asm volatile("ldmatrix.sync.aligned.m8n8.x4.trans.shared.b16 {%0,%1,%2,%3}, [%4];"
                 : "=r"(r[0]), "=r"(r[1]), "=r"(r[2]), "=r"(r[3]) : "r"(addr));
}
__device__ __forceinline__ void mma_bf16(float* c, const uint32_t* a, const uint32_t* b) {
    asm volatile("mma.sync.aligned.m16n8k16.row.col.f32.bf16.bf16.f32 "
                 "{%0,%1,%2,%3}, {%4,%5,%6,%7}, {%8,%9}, {%0,%1,%2,%3};"
                 : "+f"(c[0]), "+f"(c[1]), "+f"(c[2]), "+f"(c[3])
                 : "r"(a[0]), "r"(a[1]), "r"(a[2]), "r"(a[3]), "r"(b[0]), "r"(b[1]));
}

// ---------------- f32 -> bf16 weight convert ------------------------------------
__global__ void f2bf(const float* __restrict__ src, __nv_bfloat16* __restrict__ dst, int n) {
    int i = blockIdx.x * 256 + threadIdx.x;
    if (i < n) dst[i] = __float2bfloat16(src[i]);
}

// ---------------- LayerNorm (optional roll+window remap), bf16 out --------------
template <bool REMAP>
__global__ void ln_kernel(const float* __restrict__ xin,
                          const float* __restrict__ sc,
                          const float* __restrict__ bi,
                          __nv_bfloat16* __restrict__ xout) {
    int t = blockIdx.x;
    size_t src;
    if (REMAP) {
        int win = t / NPOS, npos = t - win * NPOS;
        int b = win >> 6, wy = (win >> 3) & 7, wx = win & 7;
        int py = npos / 7, px = npos - py * 7;
        int sy = wy * 7 + py + 3; if (sy >= 56) sy -= 56;
        int sx = wx * 7 + px + 3; if (sx >= 56) sx -= 56;
        src = (size_t)b * 3136 + sy * 56 + sx;
    } else src = (size_t)t;
    const float* xp = xin + src * CDIM;
    int tid = threadIdx.x;
    float v0 = xp[tid], v1 = xp[tid + 128], v2 = xp[tid + 256];
    float s = v0 + v1 + v2, s2 = v0 * v0 + v1 * v1 + v2 * v2;
#pragma unroll
    for (int o = 16; o > 0; o >>= 1) {
        s  += __shfl_down_sync(0xffffffffu, s,  o);
        s2 += __shfl_down_sync(0xffffffffu, s2, o);
    }
    __shared__ float sh[8];
    int w = tid >> 5;
    if ((tid & 31) == 0) { sh[w] = s; sh[4 + w] = s2; }
    __syncthreads();
    float S = sh[0] + sh[1] + sh[2] + sh[3];
    float S2 = sh[4] + sh[5] + sh[6] + sh[7];
    float mu = S * (1.0f / CDIM);
    float var = S2 * (1.0f / CDIM) - mu * mu;
    float r = rsqrtf(var + 1e-6f);
    __nv_bfloat16* op = xout + (size_t)t * CDIM;
    op[tid]       = __float2bfloat16((v0 - mu) * r * sc[tid]       + bi[tid]);
    op[tid + 128] = __float2bfloat16((v1 - mu) * r * sc[tid + 128] + bi[tid + 128]);
    op[tid + 256] = __float2bfloat16((v2 - mu) * r * sc[tid + 256] + bi[tid + 256]);
}

// ---------------- windowed attention (bf16 in/out, fp32 math) -------------------
__global__ void attn_kernel(const __nv_bfloat16* __restrict__ qkv,
                            __nv_bfloat16* __restrict__ out) {
    int blk = blockIdx.x;
    int win = blk / NHEAD, head = blk - win * NHEAD;
    int wy = (win >> 3) & 7, wx = win & 7;

    __shared__ float ks[NPOS * DHEAD];
    __shared__ float vs[NPOS * DHEAD];
    __shared__ float sc[NPOS * 53];
    __shared__ int   rg[NPOS];

    int tid = threadIdx.x;
    const __nv_bfloat16* base = qkv + (size_t)win * NPOS * (3 * CDIM) + head * DHEAD;

    for (int i = tid; i < NPOS * 16; i += 64) {
        int n = i >> 4, d = (i & 15) * 2;
        __nv_bfloat162 kk = *(const __nv_bfloat162*)(base + (size_t)n * (3 * CDIM) + CDIM + d);
        __nv_bfloat162 vv = *(const __nv_bfloat162*)(base + (size_t)n * (3 * CDIM) + 2 * CDIM + d);
        ks[n * 32 + d] = __low2float(kk);  ks[n * 32 + d + 1] = __high2float(kk);
        vs[n * 32 + d] = __low2float(vv);  vs[n * 32 + d + 1] = __high2float(vv);
    }
    if (tid < NPOS) {
        int py = tid / 7, px = tid - py * 7;
        int hy = wy * 7 + py, hx = wx * 7 + px;
        int cy = hy < 49 ? 0 : (hy < 53 ? 1 : 2);
        int cx = hx < 49 ? 0 : (hx < 53 ? 1 : 2);
        rg[tid] = cy * 3 + cx;
    }
    __syncthreads();

    if (tid < NPOS) {
        float q[DHEAD];
        const __nv_bfloat16* qp = base + (size_t)tid * (3 * CDIM);
#pragma unroll
        for (int d = 0; d < 16; ++d) {
            __nv_bfloat162 qq = *(const __nv_bfloat162*)(qp + 2 * d);
            q[2 * d] = __low2float(qq); q[2 * d + 1] = __high2float(qq);
        }
        int rn = rg[tid];
        const float scale = 0.17677669529663687f;
        float mx = -1e30f;
        for (int m = 0; m < NPOS; ++m) {
            const float4* kp = (const float4*)&ks[m * DHEAD];
            float s = 0.f;
#pragma unroll
            for (int d8 = 0; d8 < 8; ++d8) {
                float4 kv = kp[d8];
                s += q[d8 * 4] * kv.x + q[d8 * 4 + 1] * kv.y
                   + q[d8 * 4 + 2] * kv.z + q[d8 * 4 + 3] * kv.w;
            }
            s *= scale;
            if (rg[m] != rn) s -= 100.0f;
            sc[tid * 53 + m] = s;
            mx = fmaxf(mx, s);
        }
        float sum = 0.f;
        for (int m = 0; m < NPOS; ++m) {
            float p = __expf(sc[tid * 53 + m] - mx);
            sc[tid * 53 + m] = p; sum += p;
        }
        float inv = 1.0f / sum;
        float acc[DHEAD];
#pragma unroll
        for (int d = 0; d < DHEAD; ++d) acc[d] = 0.f;
        for (int m = 0; m < NPOS; ++m) {
            float p = sc[tid * 53 + m];
            const float4* vp = (const float4*)&vs[m * DHEAD];
#pragma unroll
            for (int d8 = 0; d8 < 8; ++d8) {
                float4 vv = vp[d8];
                acc[d8 * 4]     += p * vv.x;
                acc[d8 * 4 + 1] += p * vv.y;
                acc[d8 * 4 + 2] += p * vv.z;
                acc[d8 * 4 + 3] += p * vv.w;
            }
        }
        __nv_bfloat16* op = out + (size_t)(win * NPOS + tid) * CDIM + head * DHEAD;
#pragma unroll
        for (int d = 0; d < 16; ++d)
            *(__nv_bfloat162*)(op + 2 * d) =
                __floats2bfloat162_rn(acc[2 * d] * inv, acc[2 * d + 1] * inv);
    }
}

// ---------------- HMMA bf16 GEMM, 128x128 tile, BK=32, double buffered ----------
// A: [M][K] bf16 row-major.  B: [K][N] bf16 row-major.  C epilogues:
// EPI 0: +bias -> bf16 (qkv) | 1: gelu(+bias) -> bf16 (mlp1)
// EPI 2: +bias +res scatter(window-reverse+roll) -> f32 (proj)
// EPI 3: +bias +res -> f32 (mlp2)
__device__ __forceinline__ float gelu_tanh(float v) {
    float u = 0.7978845608028654f * (v + 0.044715f * v * v * v);
    return 0.5f * v * (1.0f + tanhf(u));
}

#define ASTRIDE 40    // bf16 elems per A smem row (80B)
#define BSTRIDE 136   // bf16 elems per B smem row (272B)

template <int EPI>
__global__ __launch_bounds__(256)
void hgemm(const __nv_bfloat16* __restrict__ A,
           const __nv_bfloat16* __restrict__ Bw,
           const float* __restrict__ bias,
           void* __restrict__ CoutV,
           const float* __restrict__ res,
           int Nn, int K) {
    __shared__ __nv_bfloat16 As[2][128 * ASTRIDE];
    __shared__ __nv_bfloat16 Bs[2][32 * BSTRIDE];

    const int tid = threadIdx.x, lane = tid & 31, warp = tid >> 5;
    const int wm = warp & 3, wn = warp >> 2;
    const int bx = blockIdx.x, by = blockIdx.y;

    const __nv_bfloat16* Ag = A  + (size_t)(by * 128) * K;
    const __nv_bfloat16* Bg = Bw + bx * 128;

    const uint32_t a_base = smem_u32(As);
    const uint32_t b_base = smem_u32(Bs);
    const uint32_t ABUF = 128 * ASTRIDE * 2;   // bytes per A stage
    const uint32_t BBUF = 32 * BSTRIDE * 2;    // bytes per B stage

    // per-thread load targets
    const int ar = (tid + 0) >> 2, ac = tid & 3;          // id j=0
    const int ar1 = (tid + 256) >> 2;                     // id j=1 (same ac)
    const int bk = tid >> 4, bc = tid & 15;               // j=0
    const int bk1 = (tid + 256) >> 4;                     // j=1 (same bc)

    auto load_stage = [&](int buf, int k0) {
        uint32_t a_s = a_base + buf * ABUF;
        uint32_t b_s = b_base + buf * BBUF;
        cp16(a_s + ar  * 80 + ac * 16, Ag + (size_t)ar  * K + k0 + ac * 8);
        cp16(a_s + ar1 * 80 + ac * 16, Ag + (size_t)ar1 * K + k0 + ac * 8);
        cp16(b_s + bk  * 272 + bc * 16, Bg + (size_t)(k0 + bk)  * Nn + bc * 8);
        cp16(b_s + bk1 * 272 + bc * 16, Bg + (size_t)(k0 + bk1) * Nn + bc * 8);
        CP_COMMIT();
    };

    float acc[2][8][4];
#pragma unroll
    for (int i = 0; i < 2; ++i)
#pragma unroll
        for (int j = 0; j < 8; ++j)
#pragma unroll
            for (int q = 0; q < 4; ++q) acc[i][j][q] = 0.f;

    const int kIters = K >> 5;
    load_stage(0, 0);

    // precomputed ldmatrix lane addresses (relative, buffer 0)
    const uint32_t a_lm = a_base + (wm * 32 + (lane & 15)) * 80 + (lane >> 4) * 16;
    const uint32_t b_lm = b_base + (lane & 15) * 272 + (wn * 64 + (lane >> 4) * 8) * 2;

    for (int i = 0; i < kIters; ++i) {
        int cur = i & 1;
        if (i + 1 < kIters) { load_stage(1 - cur, (i + 1) * 32); CP_WAIT(1); }
        else CP_WAIT(0);
        __syncthreads();

        uint32_t aS = a_lm + cur * ABUF;
        uint32_t bS = b_lm + cur * BBUF;
#pragma unroll
        for (int kk = 0; kk < 2; ++kk) {
            uint32_t a[2][4];
#pragma unroll
            for (int mi = 0; mi < 2; ++mi)
                ldsm4(a[mi], aS + mi * 16 * 80 + kk * 32);
            uint32_t b[8][2];
#pragma unroll
            for (int nq = 0; nq < 4; ++nq) {
                uint32_t t[4];
                ldsm4t(t, bS + kk * 16 * 272 + nq * 32);
                b[2 * nq][0] = t[0]; b[2 * nq][1] = t[1];
                b[2 * nq + 1][0] = t[2]; b[2 * nq + 1][1] = t[3];
            }
#pragma unroll
            for (int mi = 0; mi < 2; ++mi)
#pragma unroll
                for (int ni = 0; ni < 8; ++ni)
                    mma_bf16(acc[mi][ni], a[mi], b[ni]);
        }
        __syncthreads();
    }

    // ---------------- epilogue ----------------
    const int gid = lane >> 2, tig2 = (lane & 3) * 2;
#pragma unroll
    for (int mi = 0; mi < 2; ++mi) {
#pragma unroll
        for (int hf = 0; hf < 2; ++hf) {
            int m = by * 128 + wm * 32 + mi * 16 + gid + hf * 8;
            size_t orow_off; const float* rrow = nullptr;
            if (EPI == 2) {
                int win = m / NPOS, npos = m - win * NPOS;
                int b = win >> 6, wy = (win >> 3) & 7, wx = win & 7;
                int py = npos / 7, px = npos - py * 7;
                int yy = wy * 7 + py + 3; if (yy >= 56) yy -= 56;
                int xx = wx * 7 + px + 3; if (xx >= 56) xx -= 56;
                orow_off = ((size_t)b * 3136 + yy * 56 + xx) * (size_t)Nn;
                rrow = res + orow_off;
            } else {
                orow_off = (size_t)m * Nn;
                if (EPI == 3) rrow = res + orow_off;
            }
#pragma unroll
            for (int ni = 0; ni < 8; ++ni) {
                int n = bx * 128 + wn * 64 + ni * 8 + tig2;
                float v0 = acc[mi][ni][hf * 2 + 0] + bias[n];
                float v1 = acc[mi][ni][hf * 2 + 1] + bias[n + 1];
                if (EPI == 1) { v0 = gelu_tanh(v0); v1 = gelu_tanh(v1); }
                if (EPI == 0 || EPI == 1) {
                    *(__nv_bfloat162*)((__nv_bfloat16*)CoutV + orow_off + n) =
                        __floats2bfloat162_rn(v0, v1);
                } else {
                    v0 += rrow[n]; v1 += rrow[n + 1];
                    *(float2*)((float*)CoutV + orow_off + n) = make_float2(v0, v1);
                }
            }
        }
    }
}

// ---------------- launch ----------------------------------------------------------
extern "C" void kernel_launch(void* const* d_in, const int* in_sizes, int n_in,
                              void* d_out, int out_size) {
    const float* x     = (const float*)d_in[0];
    const float* n1s   = (const float*)d_in[1];
    const float* n1b   = (const float*)d_in[2];
    const float* qkvw  = (const float*)d_in[3];
    const float* qkvb  = (const float*)d_in[4];
    const float* projw = (const float*)d_in[5];
    const float* projb = (const float*)d_in[6];
    const float* n2s   = (const float*)d_in[7];
    const float* n2b   = (const float*)d_in[8];
    const float* w1    = (const float*)d_in[9];
    const float* b1    = (const float*)d_in[10];
    const float* w2    = (const float*)d_in[11];
    const float* b2    = (const float*)d_in[12];
    float* out = (float*)d_out;

    __nv_bfloat16 *xw, *qkv, *att, *xn2, *h1, *wqkv, *wproj, *wm1, *wm2;
    float* x2;
    cudaGetSymbolAddress((void**)&xw,   g_xw);
    cudaGetSymbolAddress((void**)&qkv,  g_qkv);
    cudaGetSymbolAddress((void**)&att,  g_att);
    cudaGetSymbolAddress((void**)&x2,   g_x2);
    cudaGetSymbolAddress((void**)&xn2,  g_xn2);
    cudaGetSymbolAddress((void**)&h1,   g_h1);
    cudaGetSymbolAddress((void**)&wqkv, g_wqkv);
    cudaGetSymbolAddress((void**)&wproj,g_wproj);
    cudaGetSymbolAddress((void**)&wm1,  g_wm1);
    cudaGetSymbolAddress((void**)&wm2,  g_wm2);

    // weight converts (f32 -> bf16, layout unchanged [K][N])
    f2bf<<<(CDIM * 3 * CDIM + 255) / 256, 256>>>(qkvw, wqkv, CDIM * 3 * CDIM);
    f2bf<<<(CDIM * CDIM + 255) / 256, 256>>>(projw, wproj, CDIM * CDIM);
    f2bf<<<(CDIM * HID + 255) / 256, 256>>>(w1, wm1, CDIM * HID);
    f2bf<<<(HID * CDIM + 255) / 256, 256>>>(w2, wm2, HID * CDIM);

    // 1. LN1 + roll + window partition -> bf16
    ln_kernel<true><<<TOK, 128>>>(x, n1s, n1b, xw);
    // 2. QKV: (TOK x 384) @ (384 x 1152)
    hgemm<0><<<dim3(1152 / 128, TOK / 128), 256>>>(xw, wqkv, qkvb, qkv, nullptr, 1152, CDIM);
    // 3. attention
    attn_kernel<<<NWIN * NHEAD, 64>>>(qkv, att);
    // 4. proj + scatter + residual -> x2 (f32)
    hgemm<2><<<dim3(CDIM / 128, TOK / 128), 256>>>(att, wproj, projb, x2, x, CDIM, CDIM);
    // 5. LN2 -> bf16
    ln_kernel<false><<<TOK, 128>>>(x2, n2s, n2b, xn2);
    // 6. MLP1 + gelu -> bf16
    hgemm<1><<<dim3(HID / 128, TOK / 128), 256>>>(xn2, wm1, b1, h1, nullptr, HID, CDIM);
    // 7. MLP2 + residual -> out (f32)
    hgemm<3><<<dim3(CDIM / 128, TOK / 128), 256>>>(h1, wm2, b2, out, x2, CDIM, HID);
}

// round 6
// speedup vs baseline: 4.7348x; 1.0528x over previous
#include <cuda_runtime.h>
#include <cuda_bf16.h>
#include <cstdint>
#include <math.h>

#define TOK   200704
#define CDIM  384
#define NHEAD 12
#define DHEAD 32
#define NWIN  4096
#define NPOS  49
#define HID   1536

// ---------------- static scratch ----------------------------------------------
__device__ __nv_bfloat16 g_xw [(size_t)TOK * CDIM];
__device__ __nv_bfloat16 g_qkv[(size_t)TOK * 3 * CDIM];
__device__ __nv_bfloat16 g_att[(size_t)TOK * CDIM];
__device__ float         g_x2 [(size_t)TOK * CDIM];
__device__ __nv_bfloat16 g_xn2[(size_t)TOK * CDIM];
__device__ __nv_bfloat16 g_h1 [(size_t)TOK * HID];
__device__ __nv_bfloat16 g_wqkv [CDIM * 3 * CDIM];   // [K][N] bf16
__device__ __nv_bfloat16 g_wproj[CDIM * CDIM];
__device__ __nv_bfloat16 g_wm1  [CDIM * HID];
__device__ __nv_bfloat16 g_wm2  [HID * CDIM];

// ---------------- helpers -------------------------------------------------------
__device__ __forceinline__ uint32_t smem_u32(const void* p) {
    uint32_t a;
    asm("{ .reg .u64 t; cvta.to.shared.u64 t, %1; cvt.u32.u64 %0, t; }" : "=r"(a) : "l"(p));
    return a;
}
__device__ __forceinline__ void cp16(uint32_t dst, const void* src) {
    asm volatile("cp.async.cg.shared.global [%0], [%1], 16;" :: "r"(dst), "l"(src));
}
#define CP_COMMIT() asm volatile("cp.async.commit_group;" ::: "memory")
#define CP_WAIT(n)  asm volatile("cp.async.wait_group %0;" :: "n"(n) : "memory")

__device__ __forceinline__ void ldsm4(uint32_t* r, uint32_t addr) {
    asm volatile("ldmatrix.sync.aligned.m8n8.x4.shared.b16 {%0,%1,%2,%3}, [%4];"
                 : "=r"(r[0]), "=r"(r[1]), "=r"(r[2]), "=r"(r[3]) : "r"(addr));
}
__device__ __forceinline__ void ldsm4t(uint32_t* r, uint32_t addr) {
    asm volatile("ldmatrix.sync.aligned.m8n8.x4.trans.shared.b16 {%0,%1,%2,%3}, [%4];"
                 : "=r"(r[0]), "=r"(r[1]), "=r"(r[2]), "=r"(r[3]) : "r"(addr));
}
__device__ __forceinline__ void mma_bf16(float* c, const uint32_t* a, const uint32_t* b) {
    asm volatile("mma.sync.aligned.m16n8k16.row.col.f32.bf16.bf16.f32 "
                 "{%0,%1,%2,%3}, {%4,%5,%6,%7}, {%8,%9}, {%0,%1,%2,%3};"
                 : "+f"(c[0]), "+f"(c[1]), "+f"(c[2]), "+f"(c[3])
                 : "r"(a[0]), "r"(a[1]), "r"(a[2]), "r"(a[3]), "r"(b[0]), "r"(b[1]));
}

// ---------------- f32 -> bf16 weight convert ------------------------------------
__global__ void f2bf(const float* __restrict__ src, __nv_bfloat16* __restrict__ dst, int n) {
    int i = blockIdx.x * 256 + threadIdx.x;
    if (i < n) dst[i] = __float2bfloat16(src[i]);
}

// ---------------- LayerNorm (optional roll+window remap), bf16 out --------------
template <bool REMAP>
__global__ void ln_kernel(const float* __restrict__ xin,
                          const float* __restrict__ sc,
                          const float* __restrict__ bi,
                          __nv_bfloat16* __restrict__ xout) {
    int t = blockIdx.x;
    size_t src;
    if (REMAP) {
        int win = t / NPOS, npos = t - win * NPOS;
        int b = win >> 6, wy = (win >> 3) & 7, wx = win & 7;
        int py = npos / 7, px = npos - py * 7;
        int sy = wy * 7 + py + 3; if (sy >= 56) sy -= 56;
        int sx = wx * 7 + px + 3; if (sx >= 56) sx -= 56;
        src = (size_t)b * 3136 + sy * 56 + sx;
    } else src = (size_t)t;
    const float* xp = xin + src * CDIM;
    int tid = threadIdx.x;
    float v0 = xp[tid], v1 = xp[tid + 128], v2 = xp[tid + 256];
    float s = v0 + v1 + v2, s2 = v0 * v0 + v1 * v1 + v2 * v2;
#pragma unroll
    for (int o = 16; o > 0; o >>= 1) {
        s  += __shfl_down_sync(0xffffffffu, s,  o);
        s2 += __shfl_down_sync(0xffffffffu, s2, o);
    }
    __shared__ float sh[8];
    int w = tid >> 5;
    if ((tid & 31) == 0) { sh[w] = s; sh[4 + w] = s2; }
    __syncthreads();
    float S = sh[0] + sh[1] + sh[2] + sh[3];
    float S2 = sh[4] + sh[5] + sh[6] + sh[7];
    float mu = S * (1.0f / CDIM);
    float var = S2 * (1.0f / CDIM) - mu * mu;
    float r = rsqrtf(var + 1e-6f);
    __nv_bfloat16* op = xout + (size_t)t * CDIM;
    op[tid]       = __float2bfloat16((v0 - mu) * r * sc[tid]       + bi[tid]);
    op[tid + 128] = __float2bfloat16((v1 - mu) * r * sc[tid + 128] + bi[tid + 128]);
    op[tid + 256] = __float2bfloat16((v2 - mu) * r * sc[tid + 256] + bi[tid + 256]);
}

// ---------------- windowed attention (bf16 in/out, fp32 math) -------------------
__global__ void attn_kernel(const __nv_bfloat16* __restrict__ qkv,
                            __nv_bfloat16* __restrict__ out) {
    int blk = blockIdx.x;
    int win = blk / NHEAD, head = blk - win * NHEAD;
    int wy = (win >> 3) & 7, wx = win & 7;

    __shared__ float ks[NPOS * DHEAD];
    __shared__ float vs[NPOS * DHEAD];
    __shared__ float sc[NPOS * 53];
    __shared__ int   rg[NPOS];

    int tid = threadIdx.x;
    const __nv_bfloat16* base = qkv + (size_t)win * NPOS * (3 * CDIM) + head * DHEAD;

    for (int i = tid; i < NPOS * 16; i += 64) {
        int n = i >> 4, d = (i & 15) * 2;
        __nv_bfloat162 kk = *(const __nv_bfloat162*)(base + (size_t)n * (3 * CDIM) + CDIM + d);
        __nv_bfloat162 vv = *(const __nv_bfloat162*)(base + (size_t)n * (3 * CDIM) + 2 * CDIM + d);
        ks[n * 32 + d] = __low2float(kk);  ks[n * 32 + d + 1] = __high2float(kk);
        vs[n * 32 + d] = __low2float(vv);  vs[n * 32 + d + 1] = __high2float(vv);
    }
    if (tid < NPOS) {
        int py = tid / 7, px = tid - py * 7;
        int hy = wy * 7 + py, hx = wx * 7 + px;
        int cy = hy < 49 ? 0 : (hy < 53 ? 1 : 2);
        int cx = hx < 49 ? 0 : (hx < 53 ? 1 : 2);
        rg[tid] = cy * 3 + cx;
    }
    __syncthreads();

    if (tid < NPOS) {
        float q[DHEAD];
        const __nv_bfloat16* qp = base + (size_t)tid * (3 * CDIM);
#pragma unroll
        for (int d = 0; d < 16; ++d) {
            __nv_bfloat162 qq = *(const __nv_bfloat162*)(qp + 2 * d);
            q[2 * d] = __low2float(qq); q[2 * d + 1] = __high2float(qq);
        }
        int rn = rg[tid];
        const float scale = 0.17677669529663687f;
        float mx = -1e30f;
        for (int m = 0; m < NPOS; ++m) {
            const float4* kp = (const float4*)&ks[m * DHEAD];
            float s = 0.f;
#pragma unroll
            for (int d8 = 0; d8 < 8; ++d8) {
                float4 kv = kp[d8];
                s += q[d8 * 4] * kv.x + q[d8 * 4 + 1] * kv.y
                   + q[d8 * 4 + 2] * kv.z + q[d8 * 4 + 3] * kv.w;
            }
            s *= scale;
            if (rg[m] != rn) s -= 100.0f;
            sc[tid * 53 + m] = s;
            mx = fmaxf(mx, s);
        }
        float sum = 0.f;
        for (int m = 0; m < NPOS; ++m) {
            float p = __expf(sc[tid * 53 + m] - mx);
            sc[tid * 53 + m] = p; sum += p;
        }
        float inv = 1.0f / sum;
        float acc[DHEAD];
#pragma unroll
        for (int d = 0; d < DHEAD; ++d) acc[d] = 0.f;
        for (int m = 0; m < NPOS; ++m) {
            float p = sc[tid * 53 + m];
            const float4* vp = (const float4*)&vs[m * DHEAD];
#pragma unroll
            for (int d8 = 0; d8 < 8; ++d8) {
                float4 vv = vp[d8];
                acc[d8 * 4]     += p * vv.x;
                acc[d8 * 4 + 1] += p * vv.y;
                acc[d8 * 4 + 2] += p * vv.z;
                acc[d8 * 4 + 3] += p * vv.w;
            }
        }
        __nv_bfloat16* op = out + (size_t)(win * NPOS + tid) * CDIM + head * DHEAD;
#pragma unroll
        for (int d = 0; d < 16; ++d)
            *(__nv_bfloat162*)(op + 2 * d) =
                __floats2bfloat162_rn(acc[2 * d] * inv, acc[2 * d + 1] * inv);
    }
}

// ---------------- HMMA bf16 GEMM, 128x128 tile, BK=64, 2-stage, 2 CTA/SM --------
__device__ __forceinline__ float gelu_tanh(float v) {
    float u = 0.7978845608028654f * (v + 0.044715f * v * v * v);
    return 0.5f * v * (1.0f + tanhf(u));
}

// smem (dynamic): A stages then B stages
// A stage: 128 rows x 144 B (64 bf16 + pad)  = 18432 B
// B stage: 64 rows  x 272 B (128 bf16 + pad) = 17408 B
#define ASTG 18432u
#define BSTG 17408u
#define SMEM_GEMM (2u * (ASTG + BSTG))     // 71680 B

template <int EPI>
__global__ __launch_bounds__(256, 2)
void hgemm(const __nv_bfloat16* __restrict__ A,
           const __nv_bfloat16* __restrict__ Bw,
           const float* __restrict__ bias,
           void* __restrict__ CoutV,
           const float* __restrict__ res,
           int Nn, int K) {
    extern __shared__ char smraw[];
    const uint32_t a_base = smem_u32(smraw);
    const uint32_t b_base = a_base + 2u * ASTG;

    const int tid = threadIdx.x, lane = tid & 31, warp = tid >> 5;
    const int wm = warp & 3, wn = warp >> 2;
    const int bx = blockIdx.x, by = blockIdx.y;

    const __nv_bfloat16* Ag = A  + (size_t)(by * 128) * K;
    const __nv_bfloat16* Bg = Bw + bx * 128;

    auto load_stage = [&](int buf, int k0) {
        uint32_t a_s = a_base + buf * ASTG;
        uint32_t b_s = b_base + buf * BSTG;
        // A: 128 rows x 8 chunks (16B) = 1024 chunks
#pragma unroll
        for (int j = 0; j < 4; ++j) {
            int id = tid + j * 256;
            int row = id >> 3, cc = id & 7;
            cp16(a_s + row * 144 + cc * 16, Ag + (size_t)row * K + k0 + cc * 8);
        }
        // B: 64 rows x 16 chunks (16B) = 1024 chunks  (256 B of data per row!)
#pragma unroll
        for (int j = 0; j < 4; ++j) {
            int id = tid + j * 256;
            int row = id >> 4, cc = id & 15;
            cp16(b_s + row * 272 + cc * 16, Bg + (size_t)(k0 + row) * Nn + cc * 8);
        }
        CP_COMMIT();
    };

    float acc[2][8][4];
#pragma unroll
    for (int i = 0; i < 2; ++i)
#pragma unroll
        for (int j = 0; j < 8; ++j)
#pragma unroll
            for (int q = 0; q < 4; ++q) acc[i][j][q] = 0.f;

    const int kIters = K >> 6;
    load_stage(0, 0);

    const uint32_t a_lm = a_base + (wm * 32 + (lane & 15)) * 144 + (lane >> 4) * 16;
    const uint32_t b_lm = b_base + (lane & 15) * 272 + (wn * 64 + (lane >> 4) * 8) * 2;

    for (int i = 0; i < kIters; ++i) {
        int cur = i & 1;
        if (i + 1 < kIters) { load_stage(1 - cur, (i + 1) * 64); CP_WAIT(1); }
        else CP_WAIT(0);
        __syncthreads();                    // stage `cur` visible to all threads

        uint32_t aS = a_lm + cur * ASTG;
        uint32_t bS = b_lm + cur * BSTG;
#pragma unroll
        for (int kk = 0; kk < 4; ++kk) {
            uint32_t a[2][4];
#pragma unroll
            for (int mi = 0; mi < 2; ++mi)
                ldsm4(a[mi], aS + mi * 16 * 144 + kk * 32);
            uint32_t b[8][2];
#pragma unroll
            for (int nq = 0; nq < 4; ++nq) {
                uint32_t t[4];
                ldsm4t(t, bS + kk * 16 * 272 + nq * 32);
                b[2 * nq][0] = t[0]; b[2 * nq][1] = t[1];
                b[2 * nq + 1][0] = t[2]; b[2 * nq + 1][1] = t[3];
            }
#pragma unroll
            for (int mi = 0; mi < 2; ++mi)
#pragma unroll
                for (int ni = 0; ni < 8; ++ni)
                    mma_bf16(acc[mi][ni], a[mi], b[ni]);
        }
        __syncthreads();                    // protect `cur` from next iteration's load
    }

    // ---------------- epilogue ----------------
    const int gid = lane >> 2, tig2 = (lane & 3) * 2;
#pragma unroll
    for (int mi = 0; mi < 2; ++mi) {
#pragma unroll
        for (int hf = 0; hf < 2; ++hf) {
            int m = by * 128 + wm * 32 + mi * 16 + gid + hf * 8;
            size_t orow_off; const float* rrow = nullptr;
            if (EPI == 2) {
                int win = m / NPOS, npos = m - win * NPOS;
                int b = win >> 6, wy = (win >> 3) & 7, wx = win & 7;
                int py = npos / 7, px = npos - py * 7;
                int yy = wy * 7 + py + 3; if (yy >= 56) yy -= 56;
                int xx = wx * 7 + px + 3; if (xx >= 56) xx -= 56;
                orow_off = ((size_t)b * 3136 + yy * 56 + xx) * (size_t)Nn;
                rrow = res + orow_off;
            } else {
                orow_off = (size_t)m * Nn;
                if (EPI == 3) rrow = res + orow_off;
            }
#pragma unroll
            for (int ni = 0; ni < 8; ++ni) {
                int n = bx * 128 + wn * 64 + ni * 8 + tig2;
                float v0 = acc[mi][ni][hf * 2 + 0] + bias[n];
                float v1 = acc[mi][ni][hf * 2 + 1] + bias[n + 1];
                if (EPI == 1) { v0 = gelu_tanh(v0); v1 = gelu_tanh(v1); }
                if (EPI == 0 || EPI == 1) {
                    *(__nv_bfloat162*)((__nv_bfloat16*)CoutV + orow_off + n) =
                        __floats2bfloat162_rn(v0, v1);
                } else {
                    v0 += rrow[n]; v1 += rrow[n + 1];
                    *(float2*)((float*)CoutV + orow_off + n) = make_float2(v0, v1);
                }
            }
        }
    }
}

// ---------------- launch ----------------------------------------------------------
extern "C" void kernel_launch(void* const* d_in, const int* in_sizes, int n_in,
                              void* d_out, int out_size) {
    const float* x     = (const float*)d_in[0];
    const float* n1s   = (const float*)d_in[1];
    const float* n1b   = (const float*)d_in[2];
    const float* qkvw  = (const float*)d_in[3];
    const float* qkvb  = (const float*)d_in[4];
    const float* projw = (const float*)d_in[5];
    const float* projb = (const float*)d_in[6];
    const float* n2s   = (const float*)d_in[7];
    const float* n2b   = (const float*)d_in[8];
    const float* w1    = (const float*)d_in[9];
    const float* b1    = (const float*)d_in[10];
    const float* w2    = (const float*)d_in[11];
    const float* b2    = (const float*)d_in[12];
    float* out = (float*)d_out;

    __nv_bfloat16 *xw, *qkv, *att, *xn2, *h1, *wqkv, *wproj, *wm1, *wm2;
    float* x2;
    cudaGetSymbolAddress((void**)&xw,   g_xw);
    cudaGetSymbolAddress((void**)&qkv,  g_qkv);
    cudaGetSymbolAddress((void**)&att,  g_att);
    cudaGetSymbolAddress((void**)&x2,   g_x2);
    cudaGetSymbolAddress((void**)&xn2,  g_xn2);
    cudaGetSymbolAddress((void**)&h1,   g_h1);
    cudaGetSymbolAddress((void**)&wqkv, g_wqkv);
    cudaGetSymbolAddress((void**)&wproj,g_wproj);
    cudaGetSymbolAddress((void**)&wm1,  g_wm1);
    cudaGetSymbolAddress((void**)&wm2,  g_wm2);

    static bool attr_done = false;
    if (!attr_done) {
        cudaFuncSetAttribute(hgemm<0>, cudaFuncAttributeMaxDynamicSharedMemorySize, SMEM_GEMM);
        cudaFuncSetAttribute(hgemm<1>, cudaFuncAttributeMaxDynamicSharedMemorySize, SMEM_GEMM);
        cudaFuncSetAttribute(hgemm<2>, cudaFuncAttributeMaxDynamicSharedMemorySize, SMEM_GEMM);
        cudaFuncSetAttribute(hgemm<3>, cudaFuncAttributeMaxDynamicSharedMemorySize, SMEM_GEMM);
        attr_done = true;
    }

    f2bf<<<(CDIM * 3 * CDIM + 255) / 256, 256>>>(qkvw, wqkv, CDIM * 3 * CDIM);
    f2bf<<<(CDIM * CDIM + 255) / 256, 256>>>(projw, wproj, CDIM * CDIM);
    f2bf<<<(CDIM * HID + 255) / 256, 256>>>(w1, wm1, CDIM * HID);
    f2bf<<<(HID * CDIM + 255) / 256, 256>>>(w2, wm2, HID * CDIM);

    ln_kernel<true><<<TOK, 128>>>(x, n1s, n1b, xw);
    hgemm<0><<<dim3(1152 / 128, TOK / 128), 256, SMEM_GEMM>>>(xw, wqkv, qkvb, qkv, nullptr, 1152, CDIM);
    attn_kernel<<<NWIN * NHEAD, 64>>>(qkv, att);
    hgemm<2><<<dim3(CDIM / 128, TOK / 128), 256, SMEM_GEMM>>>(att, wproj, projb, x2, x, CDIM, CDIM);
    ln_kernel<false><<<TOK, 128>>>(x2, n2s, n2b, xn2);
    hgemm<1><<<dim3(HID / 128, TOK / 128), 256, SMEM_GEMM>>>(xn2, wm1, b1, h1, nullptr, HID, CDIM);
    hgemm<3><<<dim3(CDIM / 128, TOK / 128), 256, SMEM_GEMM>>>(h1, wm2, b2, out, x2, CDIM, HID);
}